// round 14
// baseline (speedup 1.0000x reference)
#include <cuda_runtime.h>
#include <cuda_fp16.h>
#include <cstdint>
#include <math.h>

typedef unsigned int u32;

// ---------------- problem constants ----------------
#define Bq     512
#define Hd     512
#define FEAT   128
#define T_ENC  512
#define PRED   96

#define GRIDSZ 128
#define NTHR   256            // 8 warps: 2(m) x 4(n), warp tile m32 x n32
#define INTHR  256
#define BM 64
#define BN 128

// ---------------- smem layout (manual, dynamic) ----------------
// chunk (K=64): A[64][144B] Wh[128][144B] Wl[128][144B]
#define RPB   144u
#define A_SZ  9216u            // 64*144
#define W_SZ  18432u           // 128*144
#define CHB   46080u           // A_SZ + 2*W_SZ
#define NBUF  4
#define GATES_OFF (NBUF * CHB)            // 184320
#define SMEM_BYTES (GATES_OFF + BM * BN * 4)  // 217088

// ---------------- persistent device state ----------------
__device__ __half g_h0[2][Bq * Hd];
__device__ __half g_h1[2][Bq * Hd];
__device__ float g_fc_part[16][Bq];
__device__ float g_dec_in0[Bq];
__device__ unsigned int g_bar;

// fp16 split weights, permuted rows: P = tileN*128 + j, orig = (j/32)*512 + tileN*32 + (j%32)
__device__ __half g_eWh0h[2048 * 512], g_eWh0l[2048 * 512];
__device__ __half g_eWi0h[2048 * 128], g_eWi0l[2048 * 128];
__device__ __half g_eWi1h[2048 * 512], g_eWi1l[2048 * 512];
__device__ __half g_eWh1h[2048 * 512], g_eWh1l[2048 * 512];
__device__ __half g_dWh0h[2048 * 512], g_dWh0l[2048 * 512];
__device__ __half g_dWi1h[2048 * 512], g_dWi1l[2048 * 512];
__device__ __half g_dWh1h[2048 * 512], g_dWh1l[2048 * 512];
__device__ __half g_X[Bq * T_ENC * FEAT];

// ---------------- helpers ----------------
__device__ __forceinline__ u32 smem_u32(const void* p) {
    return (u32)__cvta_generic_to_shared(const_cast<void*>(p));
}
__device__ __forceinline__ void ldsm4(u32* r, u32 addr) {
    asm volatile("ldmatrix.sync.aligned.m8n8.x4.shared.b16 {%0,%1,%2,%3},[%4];"
                 : "=r"(r[0]), "=r"(r[1]), "=r"(r[2]), "=r"(r[3]) : "r"(addr));
}
__device__ __forceinline__ void mma16816(float* c, const u32* a, const u32* b) {
    asm volatile("mma.sync.aligned.m16n8k16.row.col.f32.f16.f16.f32 "
                 "{%0,%1,%2,%3},{%4,%5,%6,%7},{%8,%9},{%0,%1,%2,%3};"
                 : "+f"(c[0]), "+f"(c[1]), "+f"(c[2]), "+f"(c[3])
                 : "r"(a[0]), "r"(a[1]), "r"(a[2]), "r"(a[3]), "r"(b[0]), "r"(b[1]));
}
#define CP16(d, s)  asm volatile("cp.async.cg.shared.global [%0], [%1], 16;" :: "r"(d), "l"(s) : "memory")
#define CPCOMMIT()  asm volatile("cp.async.commit_group;" ::: "memory")
#define CPWAIT0()   asm volatile("cp.async.wait_group 0;" ::: "memory")
#define CPWAIT1()   asm volatile("cp.async.wait_group 1;" ::: "memory")
#define CPWAIT2()   asm volatile("cp.async.wait_group 2;" ::: "memory")

__device__ __forceinline__ float sigmoid_fast(float x) {
    return __fdividef(1.0f, 1.0f + __expf(-x));
}
__device__ __forceinline__ float tanh_fast(float x) {
    const float t = __expf(-2.0f * fabsf(x));
    const float r = __fdividef(1.0f - t, 1.0f + t);
    return x < 0.0f ? -r : r;
}

__device__ __forceinline__ void grid_bar(unsigned int* phase) {
    __syncthreads();
    if (threadIdx.x == 0) {
        __threadfence();
        atomicAdd(&g_bar, 1u);
        ++(*phase);
        const unsigned int target = (*phase) * (unsigned int)GRIDSZ;
        for (;;) {
            unsigned int v;
            asm volatile("ld.global.acquire.gpu.u32 %0, [%1];" : "=r"(v) : "l"(&g_bar));
            if (v >= target) break;
            __nanosleep(32);
        }
    }
    __syncthreads();
}

// ---------------- W prefetch for next stage (pre-barrier, uncommitted) ----------
// Queues W (hi+lo) for chunks 0..2 of the NEXT pipe's seg0 (stride 512) into
// slots 0..2. Safe: all chunk-slot readers of the previous pipe finished before
// the preceding epilogue's first __syncthreads; gates live in a separate region.
__device__ __forceinline__ void prefetch_w3(char* smem,
                                            const __half* __restrict__ Wh,
                                            const __half* __restrict__ Wl) {
    const int tid = threadIdx.x;
    const u32 base = smem_u32(smem);
    const int r0 = tid >> 3;
    const int c8 = (tid & 7) << 3;
    const __half* gWh = Wh + (size_t)r0 * 512 + c8;
    const __half* gWl = Wl + (size_t)r0 * 512 + c8;
    const size_t w32 = (size_t)32 * 512;
    const u32 dW0 = base + A_SZ + (u32)r0 * RPB + (u32)c8 * 2;
    const u32 dW1 = dW0 + W_SZ;
#pragma unroll
    for (int c = 0; c < 3; ++c) {
        const u32 o = (u32)c * CHB;
        const int k0 = c << 6;
#pragma unroll
        for (int k = 0; k < 4; ++k) {
            CP16(dW0 + o + (u32)k * 32 * RPB, gWh + k0 + (size_t)k * w32);
            CP16(dW1 + o + (u32)k * 32 * RPB, gWl + k0 + (size_t)k * w32);
        }
    }
    // no commit: folded into gemm_pipe's first groups
}

// ---------------- fused multi-segment tensor-core GEMM pipeline -----------------
// Up to 4 segments stream through one 4-deep cp.async pipeline; chunks < accSplit
// accumulate into acc0, the rest into acc1. fp16 2-pass (W hi/lo, A single limb).
// Segment W strides FIXED: seg0=512, seg1=128 (X@Wi0 only), seg2=512, seg3=512.
// preW=1: W for chunks 0..2 (all within seg0; requires nc0>=3) was queued
// uncommitted pre-barrier; prologue issues A-only with one commit per chunk,
// preserving chunk c <-> group c mapping.
__device__ __forceinline__ void gemm_pipe(
        float acc0[2][4][4], float acc1[2][4][4], char* smem,
        const __half* A0, size_t lda0, const __half* W0h, const __half* W0l, int nc0,
        const __half* A1, size_t lda1, const __half* W1h, const __half* W1l, int nc1,
        const __half* A2, size_t lda2, const __half* W2h, const __half* W2l, int nc2,
        const __half* A3, size_t lda3, const __half* W3h, const __half* W3l, int nc3,
        int accSplit, int bm0, int preW)
{
    const int tid = threadIdx.x, lane = tid & 31, wid = tid >> 5;
    const int wm = wid & 1, wn = wid >> 1;
    const u32 base = smem_u32(smem);

    const int r0 = tid >> 3;            // 0..31
    const int c8 = (tid & 7) << 3;      // 0..56 elems

    const __half* gA0 = A0 + (size_t)(bm0 + r0) * lda0 + c8;
    const __half* gA1 = A1 ? A1 + (size_t)(bm0 + r0) * lda1 + c8 : gA0;
    const __half* gA2 = A2 ? A2 + (size_t)(bm0 + r0) * lda2 + c8 : gA0;
    const __half* gA3 = A3 ? A3 + (size_t)(bm0 + r0) * lda3 + c8 : gA0;
    const size_t a0s = (size_t)32 * lda0, a1s = (size_t)32 * lda1;
    const size_t a2s = (size_t)32 * lda2, a3s = (size_t)32 * lda3;

    const __half* gW0h = W0h + (size_t)r0 * 512 + c8;
    const __half* gW0l = W0l + (size_t)r0 * 512 + c8;
    const __half* gW1h = W1h ? W1h + (size_t)r0 * 128 + c8 : gW0h;
    const __half* gW1l = W1l ? W1l + (size_t)r0 * 128 + c8 : gW0l;
    const __half* gW2h = W2h ? W2h + (size_t)r0 * 512 + c8 : gW0h;
    const __half* gW2l = W2l ? W2l + (size_t)r0 * 512 + c8 : gW0l;
    const __half* gW3h = W3h ? W3h + (size_t)r0 * 512 + c8 : gW0h;
    const __half* gW3l = W3l ? W3l + (size_t)r0 * 512 + c8 : gW0l;
    const size_t w512 = (size_t)32 * 512, w128 = (size_t)32 * 128;

    const u32 dA  = base + (u32)r0 * RPB + (u32)c8 * 2;
    const u32 dW0 = base + A_SZ + (u32)r0 * RPB + (u32)c8 * 2;
    const u32 dW1 = dW0 + W_SZ;

    const int e0 = nc0, e1 = e0 + nc1, e2 = e1 + nc2, e3 = e2 + nc3;
    const int nc = e3;

#define ISSUE_SEG(cl, GA, AS, GWH, GWL, WS, O) do { \
        const int _k0 = (cl) << 6; \
        CP16(dA + (O), (GA) + _k0); \
        CP16(dA + (O) + 32 * RPB, (GA) + _k0 + (AS)); \
        _Pragma("unroll") \
        for (int _k = 0; _k < 4; ++_k) { \
            CP16(dW0 + (O) + (u32)_k * 32 * RPB, (GWH) + _k0 + (size_t)_k * (WS)); \
            CP16(dW1 + (O) + (u32)_k * 32 * RPB, (GWL) + _k0 + (size_t)_k * (WS)); \
        } \
        CPCOMMIT(); \
    } while (0)

    auto issue = [&](int c) {
        const u32 o = (u32)(c & 3) * CHB;
        if (c < e0)      ISSUE_SEG(c,      gA0, a0s, gW0h, gW0l, w512, o);
        else if (c < e1) ISSUE_SEG(c - e0, gA1, a1s, gW1h, gW1l, w128, o);
        else if (c < e2) ISSUE_SEG(c - e1, gA2, a2s, gW2h, gW2l, w512, o);
        else             ISSUE_SEG(c - e2, gA3, a3s, gW3h, gW3l, w512, o);
    };

    // ldmatrix addressing (slot 0 base; add (c&3)*CHB + ks*32 per use)
    const int q = lane >> 3, l7 = lane & 7;
    const int arow = ((q & 1) << 3) + l7, acolb = (q >> 1) << 4;
    const int brow = ((q >> 1) << 3) + l7, bcolb = (q & 1) << 4;
    const u32 aH0 = base + (u32)(wm * 32 + arow) * RPB + acolb;
    const u32 aH1 = aH0 + 16 * RPB;
    const u32 bH0 = base + A_SZ + (u32)(wn * 32 + brow) * RPB + bcolb;
    const u32 bH1 = bH0 + 16 * RPB;
    const u32 bL0 = bH0 + W_SZ, bL1 = bH1 + W_SZ;

#define CHUNK_MMA(ACC, O) do { \
        _Pragma("unroll") \
        for (int _ks = 0; _ks < 4; ++_ks) { \
            const u32 _off = (O) + _ks * 32; \
            u32 _rah0[4], _rah1[4]; \
            u32 _rbh0[4], _rbh1[4], _rbl0[4], _rbl1[4]; \
            ldsm4(_rah0, aH0 + _off); ldsm4(_rah1, aH1 + _off); \
            ldsm4(_rbh0, bH0 + _off); ldsm4(_rbh1, bH1 + _off); \
            ldsm4(_rbl0, bL0 + _off); ldsm4(_rbl1, bL1 + _off); \
            mma16816((ACC)[0][0], _rah0, _rbh0); mma16816((ACC)[0][1], _rah0, _rbh0 + 2); \
            mma16816((ACC)[0][2], _rah0, _rbh1); mma16816((ACC)[0][3], _rah0, _rbh1 + 2); \
            mma16816((ACC)[1][0], _rah1, _rbh0); mma16816((ACC)[1][1], _rah1, _rbh0 + 2); \
            mma16816((ACC)[1][2], _rah1, _rbh1); mma16816((ACC)[1][3], _rah1, _rbh1 + 2); \
            mma16816((ACC)[0][0], _rah0, _rbl0); mma16816((ACC)[0][1], _rah0, _rbl0 + 2); \
            mma16816((ACC)[0][2], _rah0, _rbl1); mma16816((ACC)[0][3], _rah0, _rbl1 + 2); \
            mma16816((ACC)[1][0], _rah1, _rbl0); mma16816((ACC)[1][1], _rah1, _rbl0 + 2); \
            mma16816((ACC)[1][2], _rah1, _rbl1); mma16816((ACC)[1][3], _rah1, _rbl1 + 2); \
        } \
    } while (0)

    __syncthreads();   // prior chunk-buffer consumers done
    if (preW) {
        // W for chunks 0..2 queued pre-barrier; issue A only (chunks 0..2 in seg0)
#pragma unroll
        for (int c = 0; c < 3; ++c) {
            const u32 o = (u32)c * CHB;
            const int k0 = c << 6;
            CP16(dA + o, gA0 + k0);
            CP16(dA + o + 32 * RPB, gA0 + k0 + a0s);
            CPCOMMIT();
        }
    } else {
        issue(0);
        if (1 < nc) issue(1);
        if (2 < nc) issue(2);
    }

    for (int c = 0; c < nc; ++c) {
        if (c + 2 < nc)      { CPWAIT2(); }
        else if (c + 1 < nc) { CPWAIT1(); }
        else                 { CPWAIT0(); }
        __syncthreads();               // publish group c; all done reading c-1
        if (c + 3 < nc) issue(c + 3);  // slot (c+3)&3 == (c-1)&3: free

        const u32 o = (u32)(c & 3) * CHB;
        if (c < accSplit) { CHUNK_MMA(acc0, o); }
        else              { CHUNK_MMA(acc1, o); }
    }
}

// ---------------- epilogue: bias + LSTM pointwise ------------------------------
template <int MODE>
__device__ __forceinline__ void epilogue(float acc[2][4][4], char* smem, float cR[8],
                                         const float* __restrict__ b_ih,
                                         const float* __restrict__ b_hh,
                                         __half* __restrict__ hOut,
                                         int bm0, int hc0, int tileN,
                                         const float* __restrict__ rank1w,
                                         const float* __restrict__ y,
                                         const int* __restrict__ tf_mask,
                                         float* __restrict__ d_out, int t,
                                         const float* __restrict__ fcW,
                                         const float* __restrict__ fc_b) {
    float (*gates)[BN] = (float (*)[BN])(smem + GATES_OFF);
    const int tid = threadIdx.x;
    const int lane = tid & 31, wid = tid >> 5;
    const int wm = wid & 1, wn = wid >> 1;

    __syncthreads();   // previous epilogue's gates reads done; all CHUNK_MMA done
    {
        const int r0 = wm * 32 + (lane >> 2);
        const int c0 = wn * 32 + ((lane & 3) << 1);
#pragma unroll
        for (int m = 0; m < 2; ++m)
#pragma unroll
            for (int j = 0; j < 4; ++j) {
                *(float2*)&gates[r0 + m * 16][c0 + j * 8] =
                    make_float2(acc[m][j][0], acc[m][j][1]);
                *(float2*)&gates[r0 + m * 16 + 8][c0 + j * 8] =
                    make_float2(acc[m][j][2], acc[m][j][3]);
            }
    }
    __syncthreads();

    const int pc  = tid & 31;
    const int pr0 = (tid >> 5) * 8;
    const int col = hc0 + pc;

    const float bi = b_ih[col]        + b_hh[col];
    const float bf = b_ih[512 + col]  + b_hh[512 + col];
    const float bg = b_ih[1024 + col] + b_hh[1024 + col];
    const float bo = b_ih[1536 + col] + b_hh[1536 + col];

    float w1i = 0.f, w1f = 0.f, w1g = 0.f, w1o = 0.f, fcw = 0.f;
    if (MODE == 1) {
        w1i = rank1w[col];
        w1f = rank1w[512 + col];
        w1g = rank1w[1024 + col];
        w1o = rank1w[1536 + col];
    }
    if (MODE == 2) fcw = fcW[col];

    const bool tfprev = (MODE == 1 && t > 0) ? (tf_mask[t - 1] != 0) : false;

#pragma unroll
    for (int qq = 0; qq < 8; ++qq) {
        const int r = pr0 + qq;
        const int b = bm0 + r;

        float xi = gates[r][pc]      + bi;
        float xf = gates[r][32 + pc] + bf;
        float xg = gates[r][64 + pc] + bg;
        float xo = gates[r][96 + pc] + bo;

        if (MODE == 1) {
            float din;
            if (t == 0) {
                din = g_dec_in0[b];
            } else {
                float out = fc_b[0];
#pragma unroll
                for (int j = 0; j < 16; ++j) out += g_fc_part[j][b];
                if (tileN == 0 && pc == 0) d_out[b * PRED + (t - 1)] = out;
                din = tfprev ? y[b * PRED + t] : out;
            }
            xi += din * w1i;
            xf += din * w1f;
            xg += din * w1g;
            xo += din * w1o;
        }

        const float ii = sigmoid_fast(xi);
        const float ff = sigmoid_fast(xf);
        const float gg = tanh_fast(xg);
        const float oo = sigmoid_fast(xo);
        const float c  = ff * cR[qq] + ii * gg;
        cR[qq] = c;
        const float h = oo * tanh_fast(c);

        hOut[b * Hd + col] = __float2half(h);

        if (MODE == 2) {
            float p = h * fcw;
#pragma unroll
            for (int off = 16; off > 0; off >>= 1)
                p += __shfl_xor_sync(0xFFFFFFFFu, p, off);
            if (pc == 0) g_fc_part[tileN][b] = p;
        }
    }
}

// ---------------- init: split weights (fp16 hi/lo), X fp16, zero h, seed -------
__device__ void split_w(__half* dh, __half* dl,
                        const float* __restrict__ src, int K, int gid, int stride) {
    const int total = 2048 * K;
    for (int i = gid; i < total; i += stride) {
        const int P = i / K, k = i - P * K;
        const int tn = P >> 7, j = P & 127;
        const int orig = ((j >> 5) << 9) + (tn << 5) + (j & 31);
        const float v = src[orig * K + k];
        const __half hh = __float2half_rn(v);
        dh[i] = hh;
        dl[i] = __float2half_rn(v - __half2float(hh));
    }
}

__global__ void init_kernel(const float* __restrict__ Xd, const float* __restrict__ Xe,
                            const float* __restrict__ eWi0, const float* __restrict__ eWh0,
                            const float* __restrict__ eWi1, const float* __restrict__ eWh1,
                            const float* __restrict__ dWh0, const float* __restrict__ dWi1,
                            const float* __restrict__ dWh1) {
    const int tid = threadIdx.x;
    const int gid = blockIdx.x * blockDim.x + tid;
    const int stride = gridDim.x * blockDim.x;

    const __half z = __float2half(0.f);
    for (int i = gid; i < Bq * Hd; i += stride) {
        g_h0[0][i] = z; g_h0[1][i] = z;
        g_h1[0][i] = z; g_h1[1][i] = z;
    }
    if (gid == 0) g_bar = 0u;

    {
        const int total = Bq * T_ENC * FEAT;
        for (int i = gid; i < total; i += stride)
            g_X[i] = __float2half_rn(Xe[i]);
    }

    split_w(g_eWh0h, g_eWh0l, eWh0, 512, gid, stride);
    split_w(g_eWi0h, g_eWi0l, eWi0, 128, gid, stride);
    split_w(g_eWi1h, g_eWi1l, eWi1, 512, gid, stride);
    split_w(g_eWh1h, g_eWh1l, eWh1, 512, gid, stride);
    split_w(g_dWh0h, g_dWh0l, dWh0, 512, gid, stride);
    split_w(g_dWi1h, g_dWi1l, dWi1, 512, gid, stride);
    split_w(g_dWh1h, g_dWh1l, dWh1, 512, gid, stride);

    const int b = blockIdx.x;
    if (b < Bq) {
        float s = 0.0f;
        for (int i = tid; i < PRED * 8; i += blockDim.x) s += Xd[b * PRED * 8 + i];
        __shared__ float red[INTHR];
        red[tid] = s;
        __syncthreads();
        for (int off = INTHR / 2; off > 0; off >>= 1) {
            if (tid < off) red[tid] += red[tid + off];
            __syncthreads();
        }
        if (tid == 0) g_dec_in0[b] = red[0];
    }
}

// ---------------- persistent seq2seq kernel ----------------
__global__ __launch_bounds__(NTHR, 1) void seq2seq_kernel(
    const float* __restrict__ y, const int* __restrict__ tfm,
    const float* __restrict__ ebi0, const float* __restrict__ ebh0,
    const float* __restrict__ ebi1, const float* __restrict__ ebh1,
    const float* __restrict__ dWi0,
    const float* __restrict__ dbi0, const float* __restrict__ dbh0,
    const float* __restrict__ dbi1, const float* __restrict__ dbh1,
    const float* __restrict__ fcW, const float* __restrict__ fcB,
    float* __restrict__ d_out) {
    extern __shared__ __align__(128) char s_raw[];

    const int tileM = blockIdx.x >> 4;   // 0..7
    const int tileN = blockIdx.x & 15;   // 0..15
    const int bm0 = tileM * BM;
    const int hc0 = tileN * 32;
    const size_t woff512 = (size_t)tileN * 128 * 512;
    const size_t woff128 = (size_t)tileN * 128 * 128;

    float c0r[8], c1r[8];
#pragma unroll
    for (int qq = 0; qq < 8; ++qq) { c0r[qq] = 0.0f; c1r[qq] = 0.0f; }

    unsigned int phase = 0;
    int par = 0;
    float acc0[2][4][4], acc1[2][4][4];

#define ZERO_ACC(A) do { _Pragma("unroll") for (int _m = 0; _m < 2; ++_m) \
    _Pragma("unroll") for (int _j = 0; _j < 4; ++_j) \
    _Pragma("unroll") for (int _k = 0; _k < 4; ++_k) (A)[_m][_j][_k] = 0.0f; } while (0)

    // ---------------- encoder (wavefront: layer0(t=s) + layer1(t=s-1)) ----------
    for (int s = 0; s < T_ENC; ++s) {
        const __half* hr0 = g_h0[par];
        __half* hw0 = g_h0[par ^ 1];
        const __half* hr1 = g_h1[par];
        __half* hw1 = g_h1[par ^ 1];

        ZERO_ACC(acc0);
        if (s > 0) {
            ZERO_ACC(acc1);
            // one fused pipeline: [h0@eWh0 | x@eWi0] -> acc0 ; [h0@eWi1 | h1@eWh1] -> acc1
            gemm_pipe(acc0, acc1, s_raw,
                      hr0, Hd, g_eWh0h + woff512, g_eWh0l + woff512, 8,
                      g_X + (size_t)s * FEAT, (size_t)T_ENC * FEAT,
                      g_eWi0h + woff128, g_eWi0l + woff128, 2,
                      hr0, Hd, g_eWi1h + woff512, g_eWi1l + woff512, 8,
                      hr1, Hd, g_eWh1h + woff512, g_eWh1l + woff512, 8,
                      10, bm0, 1);
            epilogue<0>(acc0, s_raw, c0r, ebi0, ebh0, hw0, bm0, hc0, tileN,
                        (const float*)0, (const float*)0, (const int*)0, (float*)0, s,
                        (const float*)0, (const float*)0);
            epilogue<0>(acc1, s_raw, c1r, ebi1, ebh1, hw1, bm0, hc0, tileN,
                        (const float*)0, (const float*)0, (const int*)0, (float*)0, s,
                        (const float*)0, (const float*)0);
        } else {
            gemm_pipe(acc0, acc0, s_raw,
                      hr0, Hd, g_eWh0h + woff512, g_eWh0l + woff512, 8,
                      g_X + (size_t)s * FEAT, (size_t)T_ENC * FEAT,
                      g_eWi0h + woff128, g_eWi0l + woff128, 2,
                      (const __half*)0, 0, (const __half*)0, (const __half*)0, 0,
                      (const __half*)0, 0, (const __half*)0, (const __half*)0, 0,
                      10, bm0, 0);
            epilogue<0>(acc0, s_raw, c0r, ebi0, ebh0, hw0, bm0, hc0, tileN,
                        (const float*)0, (const float*)0, (const int*)0, (float*)0, s,
                        (const float*)0, (const float*)0);
        }
        // prefetch next pipe's seg0 W across the barrier
        if (s + 1 < T_ENC)
            prefetch_w3(s_raw, g_eWh0h + woff512, g_eWh0l + woff512);
        else
            prefetch_w3(s_raw, g_eWi1h + woff512, g_eWi1l + woff512);
        grid_bar(&phase);
        par ^= 1;
    }

    // tail stage: layer1(t=T_ENC-1), plus copy final h0 across double buffer
    // (second K=512 segment in slot 2, stride 512)
    {
        const __half* hr0 = g_h0[par];
        __half* hw0 = g_h0[par ^ 1];
        const __half* hr1 = g_h1[par];
        __half* hw1 = g_h1[par ^ 1];

        ZERO_ACC(acc0);
        gemm_pipe(acc0, acc0, s_raw,
                  hr0, Hd, g_eWi1h + woff512, g_eWi1l + woff512, 8,
                  (const __half*)0, 0, (const __half*)0, (const __half*)0, 0,
                  hr1, Hd, g_eWh1h + woff512, g_eWh1l + woff512, 8,
                  (const __half*)0, 0, (const __half*)0, (const __half*)0, 0,
                  16, bm0, 1);
        epilogue<0>(acc0, s_raw, c1r, ebi1, ebh1, hw1, bm0, hc0, tileN,
                    (const float*)0, (const float*)0, (const int*)0, (float*)0, T_ENC,
                    (const float*)0, (const float*)0);

        for (int i = threadIdx.x; i < BM * 32; i += NTHR) {
            const int r = bm0 + (i >> 5), cc = hc0 + (i & 31);
            hw0[r * Hd + cc] = hr0[r * Hd + cc];
        }
        prefetch_w3(s_raw, g_dWh0h + woff512, g_dWh0l + woff512);
        grid_bar(&phase);
        par ^= 1;
    }

    // ---------------- decoder ----------------
    for (int t = 0; t < PRED; ++t) {
        const __half* hr0 = g_h0[par];
        __half* hw0 = g_h0[par ^ 1];
        const __half* hr1 = g_h1[par];
        __half* hw1 = g_h1[par ^ 1];

        // stage A: gates0 = h0 @ dWh0^T  (+ din * dWi0 in epilogue)
        ZERO_ACC(acc0);
        gemm_pipe(acc0, acc0, s_raw,
                  hr0, Hd, g_dWh0h + woff512, g_dWh0l + woff512, 8,
                  (const __half*)0, 0, (const __half*)0, (const __half*)0, 0,
                  (const __half*)0, 0, (const __half*)0, (const __half*)0, 0,
                  (const __half*)0, 0, (const __half*)0, (const __half*)0, 0,
                  8, bm0, 1);
        epilogue<1>(acc0, s_raw, c0r, dbi0, dbh0, hw0, bm0, hc0, tileN,
                    dWi0, y, tfm, d_out, t, (const float*)0, fcB);
        prefetch_w3(s_raw, g_dWi1h + woff512, g_dWi1l + woff512);
        grid_bar(&phase);

        // stage B
        ZERO_ACC(acc0);
        gemm_pipe(acc0, acc0, s_raw,
                  hw0, Hd, g_dWi1h + woff512, g_dWi1l + woff512, 8,
                  (const __half*)0, 0, (const __half*)0, (const __half*)0, 0,
                  hr1, Hd, g_dWh1h + woff512, g_dWh1l + woff512, 8,
                  (const __half*)0, 0, (const __half*)0, (const __half*)0, 0,
                  16, bm0, 1);
        epilogue<2>(acc0, s_raw, c1r, dbi1, dbh1, hw1, bm0, hc0, tileN,
                    (const float*)0, (const float*)0, (const int*)0, (float*)0, t,
                    fcW, (const float*)0);
        if (t + 1 < PRED)
            prefetch_w3(s_raw, g_dWh0h + woff512, g_dWh0l + woff512);
        grid_bar(&phase);
        par ^= 1;
    }

    // ---------------- final output (t = PRED-1) ----------------
    if (tileN == 0 && threadIdx.x < BM) {
        const int b = bm0 + threadIdx.x;
        float out = fcB[0];
#pragma unroll
        for (int j = 0; j < 16; ++j) out += g_fc_part[j][b];
        d_out[b * PRED + (PRED - 1)] = out;
    }
}

// ---------------- harness entry ----------------
extern "C" void kernel_launch(void* const* d_in, const int* in_sizes, int n_in,
                              void* d_out, int out_size) {
    const float* Xe  = (const float*)d_in[0];
    const float* Xd  = (const float*)d_in[1];
    const float* y   = (const float*)d_in[2];
    const int*   tfm = (const int*)d_in[3];
    const float* eWi0 = (const float*)d_in[4];
    const float* eWh0 = (const float*)d_in[5];
    const float* ebi0 = (const float*)d_in[6];
    const float* ebh0 = (const float*)d_in[7];
    const float* eWi1 = (const float*)d_in[8];
    const float* eWh1 = (const float*)d_in[9];
    const float* ebi1 = (const float*)d_in[10];
    const float* ebh1 = (const float*)d_in[11];
    const float* dWi0 = (const float*)d_in[12];
    const float* dWh0 = (const float*)d_in[13];
    const float* dbi0 = (const float*)d_in[14];
    const float* dbh0 = (const float*)d_in[15];
    const float* dWi1 = (const float*)d_in[16];
    const float* dWh1 = (const float*)d_in[17];
    const float* dbi1 = (const float*)d_in[18];
    const float* dbh1 = (const float*)d_in[19];
    const float* fcW  = (const float*)d_in[20];
    const float* fcB  = (const float*)d_in[21];
    float* out = (float*)d_out;

    cudaFuncSetAttribute(seq2seq_kernel,
                         cudaFuncAttributeMaxDynamicSharedMemorySize, SMEM_BYTES);

    init_kernel<<<1024, INTHR>>>(Xd, Xe, eWi0, eWh0, eWi1, eWh1, dWh0, dWi1, dWh1);
    seq2seq_kernel<<<GRIDSZ, NTHR, SMEM_BYTES>>>(y, tfm,
                                                 ebi0, ebh0, ebi1, ebh1,
                                                 dWi0, dbi0, dbh0, dbi1, dbh1,
                                                 fcW, fcB, out);
}

// round 15
// speedup vs baseline: 1.0516x; 1.0516x over previous
#include <cuda_runtime.h>
#include <cuda_fp16.h>
#include <cstdint>
#include <math.h>

typedef unsigned int u32;

// ---------------- problem constants ----------------
#define Bq     512
#define Hd     512
#define FEAT   128
#define T_ENC  512
#define PRED   96

#define GRIDSZ 256             // 8 M-tiles x 32 N-bands; 2 CTAs co-resident per SM
#define NTHR   256             // 8 warps: 2(m) x 4(n), warp tile m32 x n16
#define INTHR  256
#define BM 64
#define BN 64                  // gate cols per CTA = 4 gates x 16 h-cols
#define GST 68                 // gates row stride (floats)

// ---------------- smem layout (manual, dynamic) ----------------
// chunk (K=64): A[64][144B] Wh[64][144B] Wl[64][144B]
#define RPB   144u
#define A_SZ  9216u            // 64*144
#define W_SZ  9216u            // 64*144
#define CHB   27648u           // A_SZ + 2*W_SZ
#define NBUF  4
#define SMEM_BYTES (NBUF * CHB)   // 110592 -> 2 CTAs/SM
// gates alias chunk slot 0 (17408 B < CHB), guarded by epilogue syncs

// ---------------- persistent device state ----------------
__device__ __half g_h0[2][Bq * Hd];
__device__ __half g_h1[2][Bq * Hd];
__device__ float g_fc_part[32][Bq];
__device__ float g_dec_in0[Bq];
__device__ unsigned int g_bar;

// fp16 split weights, permuted rows: P = tileN*64 + j (tileN 0..31, j 0..63),
// orig = (j/16)*512 + tileN*16 + (j%16)
__device__ __half g_eWh0h[2048 * 512], g_eWh0l[2048 * 512];
__device__ __half g_eWi0h[2048 * 128], g_eWi0l[2048 * 128];
__device__ __half g_eWi1h[2048 * 512], g_eWi1l[2048 * 512];
__device__ __half g_eWh1h[2048 * 512], g_eWh1l[2048 * 512];
__device__ __half g_dWh0h[2048 * 512], g_dWh0l[2048 * 512];
__device__ __half g_dWi1h[2048 * 512], g_dWi1l[2048 * 512];
__device__ __half g_dWh1h[2048 * 512], g_dWh1l[2048 * 512];
__device__ __half g_X[Bq * T_ENC * FEAT];

// ---------------- helpers ----------------
__device__ __forceinline__ u32 smem_u32(const void* p) {
    return (u32)__cvta_generic_to_shared(const_cast<void*>(p));
}
__device__ __forceinline__ void ldsm4(u32* r, u32 addr) {
    asm volatile("ldmatrix.sync.aligned.m8n8.x4.shared.b16 {%0,%1,%2,%3},[%4];"
                 : "=r"(r[0]), "=r"(r[1]), "=r"(r[2]), "=r"(r[3]) : "r"(addr));
}
__device__ __forceinline__ void mma16816(float* c, const u32* a, const u32* b) {
    asm volatile("mma.sync.aligned.m16n8k16.row.col.f32.f16.f16.f32 "
                 "{%0,%1,%2,%3},{%4,%5,%6,%7},{%8,%9},{%0,%1,%2,%3};"
                 : "+f"(c[0]), "+f"(c[1]), "+f"(c[2]), "+f"(c[3])
                 : "r"(a[0]), "r"(a[1]), "r"(a[2]), "r"(a[3]), "r"(b[0]), "r"(b[1]));
}
#define CP16(d, s)  asm volatile("cp.async.cg.shared.global [%0], [%1], 16;" :: "r"(d), "l"(s) : "memory")
#define CPCOMMIT()  asm volatile("cp.async.commit_group;" ::: "memory")
#define CPWAIT0()   asm volatile("cp.async.wait_group 0;" ::: "memory")
#define CPWAIT1()   asm volatile("cp.async.wait_group 1;" ::: "memory")
#define CPWAIT2()   asm volatile("cp.async.wait_group 2;" ::: "memory")

__device__ __forceinline__ float sigmoid_fast(float x) {
    return __fdividef(1.0f, 1.0f + __expf(-x));
}
__device__ __forceinline__ float tanh_fast(float x) {
    const float t = __expf(-2.0f * fabsf(x));
    const float r = __fdividef(1.0f - t, 1.0f + t);
    return x < 0.0f ? -r : r;
}

__device__ __forceinline__ void grid_bar(unsigned int* phase) {
    __syncthreads();
    if (threadIdx.x == 0) {
        __threadfence();
        atomicAdd(&g_bar, 1u);
        ++(*phase);
        const unsigned int target = (*phase) * (unsigned int)GRIDSZ;
        for (;;) {
            unsigned int v;
            asm volatile("ld.global.acquire.gpu.u32 %0, [%1];" : "=r"(v) : "l"(&g_bar));
            if (v >= target) break;
            __nanosleep(32);
        }
    }
    __syncthreads();
}

// ---------------- fused multi-segment tensor-core GEMM pipeline -----------------
// Up to 4 segments, one 4-deep cp.async pipeline; chunks < accSplit -> acc0,
// rest -> acc1. fp16 2-pass (W hi/lo, A single limb). Warp tile m32 x n16.
// Segment W strides FIXED: seg0=512, seg1=128 (X@Wi0 only), seg2=512, seg3=512.
__device__ __forceinline__ void gemm_pipe(
        float acc0[2][2][4], float acc1[2][2][4], char* smem,
        const __half* A0, size_t lda0, const __half* W0h, const __half* W0l, int nc0,
        const __half* A1, size_t lda1, const __half* W1h, const __half* W1l, int nc1,
        const __half* A2, size_t lda2, const __half* W2h, const __half* W2l, int nc2,
        const __half* A3, size_t lda3, const __half* W3h, const __half* W3l, int nc3,
        int accSplit, int bm0)
{
    const int tid = threadIdx.x, lane = tid & 31, wid = tid >> 5;
    const int wm = wid & 1, wn = wid >> 1;
    const u32 base = smem_u32(smem);

    const int r0 = tid >> 3;            // 0..31 (also handles row r0+32)
    const int c8 = (tid & 7) << 3;      // 0..56 elems

    const __half* gA0 = A0 + (size_t)(bm0 + r0) * lda0 + c8;
    const __half* gA1 = A1 ? A1 + (size_t)(bm0 + r0) * lda1 + c8 : gA0;
    const __half* gA2 = A2 ? A2 + (size_t)(bm0 + r0) * lda2 + c8 : gA0;
    const __half* gA3 = A3 ? A3 + (size_t)(bm0 + r0) * lda3 + c8 : gA0;
    const size_t a0s = (size_t)32 * lda0, a1s = (size_t)32 * lda1;
    const size_t a2s = (size_t)32 * lda2, a3s = (size_t)32 * lda3;

    const __half* gW0h = W0h + (size_t)r0 * 512 + c8;
    const __half* gW0l = W0l + (size_t)r0 * 512 + c8;
    const __half* gW1h = W1h ? W1h + (size_t)r0 * 128 + c8 : gW0h;
    const __half* gW1l = W1l ? W1l + (size_t)r0 * 128 + c8 : gW0l;
    const __half* gW2h = W2h ? W2h + (size_t)r0 * 512 + c8 : gW0h;
    const __half* gW2l = W2l ? W2l + (size_t)r0 * 512 + c8 : gW0l;
    const __half* gW3h = W3h ? W3h + (size_t)r0 * 512 + c8 : gW0h;
    const __half* gW3l = W3l ? W3l + (size_t)r0 * 512 + c8 : gW0l;
    const size_t w512 = (size_t)32 * 512, w128 = (size_t)32 * 128;

    const u32 dA  = base + (u32)r0 * RPB + (u32)c8 * 2;
    const u32 dW0 = base + A_SZ + (u32)r0 * RPB + (u32)c8 * 2;
    const u32 dW1 = dW0 + W_SZ;

    const int e0 = nc0, e1 = e0 + nc1, e2 = e1 + nc2, e3 = e2 + nc3;
    const int nc = e3;

#define ISSUE_SEG(cl, GA, AS, GWH, GWL, WS, O) do { \
        const int _k0 = (cl) << 6; \
        CP16(dA + (O), (GA) + _k0); \
        CP16(dA + (O) + 32 * RPB, (GA) + _k0 + (AS)); \
        CP16(dW0 + (O), (GWH) + _k0); \
        CP16(dW0 + (O) + 32 * RPB, (GWH) + _k0 + (WS)); \
        CP16(dW1 + (O), (GWL) + _k0); \
        CP16(dW1 + (O) + 32 * RPB, (GWL) + _k0 + (WS)); \
        CPCOMMIT(); \
    } while (0)

    auto issue = [&](int c) {
        const u32 o = (u32)(c & 3) * CHB;
        if (c < e0)      ISSUE_SEG(c,      gA0, a0s, gW0h, gW0l, w512, o);
        else if (c < e1) ISSUE_SEG(c - e0, gA1, a1s, gW1h, gW1l, w128, o);
        else if (c < e2) ISSUE_SEG(c - e1, gA2, a2s, gW2h, gW2l, w512, o);
        else             ISSUE_SEG(c - e2, gA3, a3s, gW3h, gW3l, w512, o);
    };

    // ldmatrix addressing (slot 0 base; add (c&3)*CHB + ks*32 per use)
    const int q = lane >> 3, l7 = lane & 7;
    const int arow = ((q & 1) << 3) + l7, acolb = (q >> 1) << 4;
    const int brow = ((q >> 1) << 3) + l7, bcolb = (q & 1) << 4;
    const u32 aH0 = base + (u32)(wm * 32 + arow) * RPB + acolb;
    const u32 aH1 = aH0 + 16 * RPB;
    const u32 bH0 = base + A_SZ + (u32)(wn * 16 + brow) * RPB + bcolb;
    const u32 bL0 = bH0 + W_SZ;

#define CHUNK_MMA(ACC, O) do { \
        _Pragma("unroll") \
        for (int _ks = 0; _ks < 4; ++_ks) { \
            const u32 _off = (O) + _ks * 32; \
            u32 _rah0[4], _rah1[4], _rbh[4], _rbl[4]; \
            ldsm4(_rah0, aH0 + _off); ldsm4(_rah1, aH1 + _off); \
            ldsm4(_rbh, bH0 + _off); ldsm4(_rbl, bL0 + _off); \
            mma16816((ACC)[0][0], _rah0, _rbh); mma16816((ACC)[0][1], _rah0, _rbh + 2); \
            mma16816((ACC)[1][0], _rah1, _rbh); mma16816((ACC)[1][1], _rah1, _rbh + 2); \
            mma16816((ACC)[0][0], _rah0, _rbl); mma16816((ACC)[0][1], _rah0, _rbl + 2); \
            mma16816((ACC)[1][0], _rah1, _rbl); mma16816((ACC)[1][1], _rah1, _rbl + 2); \
        } \
    } while (0)

    __syncthreads();   // prior slot consumers (gates reads / previous gemm) done
    issue(0);
    if (1 < nc) issue(1);
    if (2 < nc) issue(2);

    for (int c = 0; c < nc; ++c) {
        if (c + 2 < nc)      { CPWAIT2(); }
        else if (c + 1 < nc) { CPWAIT1(); }
        else                 { CPWAIT0(); }
        __syncthreads();               // publish group c; all done reading c-1
        if (c + 3 < nc) issue(c + 3);  // slot (c+3)&3 == (c-1)&3: free

        const u32 o = (u32)(c & 3) * CHB;
        if (c < accSplit) { CHUNK_MMA(acc0, o); }
        else              { CHUNK_MMA(acc1, o); }
    }
}

// ---------------- epilogue: bias + LSTM pointwise ------------------------------
// gates alias chunk slot 0 (64 x GST floats)
template <int MODE>
__device__ __forceinline__ void epilogue(float acc[2][2][4], char* smem, float cR[4],
                                         const float* __restrict__ b_ih,
                                         const float* __restrict__ b_hh,
                                         __half* __restrict__ hOut,
                                         int bm0, int hc0, int tileN,
                                         const float* __restrict__ rank1w,
                                         const float* __restrict__ y,
                                         const int* __restrict__ tf_mask,
                                         float* __restrict__ d_out, int t,
                                         const float* __restrict__ fcW,
                                         const float* __restrict__ fc_b) {
    float (*gates)[GST] = (float (*)[GST])smem;
    const int tid = threadIdx.x;
    const int lane = tid & 31, wid = tid >> 5;
    const int wm = wid & 1, wn = wid >> 1;

    __syncthreads();   // all ldsm/gates readers done before aliasing slot 0
    {
        const int r0 = wm * 32 + (lane >> 2);
        const int c0 = wn * 16 + ((lane & 3) << 1);
#pragma unroll
        for (int m = 0; m < 2; ++m)
#pragma unroll
            for (int j = 0; j < 2; ++j) {
                *(float2*)&gates[r0 + m * 16][c0 + j * 8] =
                    make_float2(acc[m][j][0], acc[m][j][1]);
                *(float2*)&gates[r0 + m * 16 + 8][c0 + j * 8] =
                    make_float2(acc[m][j][2], acc[m][j][3]);
            }
    }
    __syncthreads();

    const int pc  = tid & 15;
    const int pr0 = (tid >> 4) * 4;
    const int col = hc0 + pc;

    const float bi = b_ih[col]        + b_hh[col];
    const float bf = b_ih[512 + col]  + b_hh[512 + col];
    const float bg = b_ih[1024 + col] + b_hh[1024 + col];
    const float bo = b_ih[1536 + col] + b_hh[1536 + col];

    float w1i = 0.f, w1f = 0.f, w1g = 0.f, w1o = 0.f, fcw = 0.f;
    if (MODE == 1) {
        w1i = rank1w[col];
        w1f = rank1w[512 + col];
        w1g = rank1w[1024 + col];
        w1o = rank1w[1536 + col];
    }
    if (MODE == 2) fcw = fcW[col];

    const bool tfprev = (MODE == 1 && t > 0) ? (tf_mask[t - 1] != 0) : false;

#pragma unroll
    for (int qq = 0; qq < 4; ++qq) {
        const int r = pr0 + qq;
        const int b = bm0 + r;

        float xi = gates[r][pc]      + bi;
        float xf = gates[r][16 + pc] + bf;
        float xg = gates[r][32 + pc] + bg;
        float xo = gates[r][48 + pc] + bo;

        if (MODE == 1) {
            float din;
            if (t == 0) {
                din = g_dec_in0[b];
            } else {
                float out = fc_b[0];
#pragma unroll
                for (int j = 0; j < 32; ++j) out += g_fc_part[j][b];
                if (tileN == 0 && pc == 0) d_out[b * PRED + (t - 1)] = out;
                din = tfprev ? y[b * PRED + t] : out;
            }
            xi += din * w1i;
            xf += din * w1f;
            xg += din * w1g;
            xo += din * w1o;
        }

        const float ii = sigmoid_fast(xi);
        const float ff = sigmoid_fast(xf);
        const float gg = tanh_fast(xg);
        const float oo = sigmoid_fast(xo);
        const float c  = ff * cR[qq] + ii * gg;
        cR[qq] = c;
        const float h = oo * tanh_fast(c);

        hOut[b * Hd + col] = __float2half(h);

        if (MODE == 2) {
            float p = h * fcw;
#pragma unroll
            for (int off = 8; off > 0; off >>= 1)
                p += __shfl_xor_sync(0xFFFFFFFFu, p, off);
            if (pc == 0) g_fc_part[tileN][b] = p;
        }
    }
}

// ---------------- init: split weights (fp16 hi/lo), X fp16, zero h, seed -------
__device__ void split_w(__half* dh, __half* dl,
                        const float* __restrict__ src, int K, int gid, int stride) {
    const int total = 2048 * K;
    for (int i = gid; i < total; i += stride) {
        const int P = i / K, k = i - P * K;
        const int tn = P >> 6, j = P & 63;
        const int orig = ((j >> 4) << 9) + (tn << 4) + (j & 15);
        const float v = src[orig * K + k];
        const __half hh = __float2half_rn(v);
        dh[i] = hh;
        dl[i] = __float2half_rn(v - __half2float(hh));
    }
}

__global__ void init_kernel(const float* __restrict__ Xd, const float* __restrict__ Xe,
                            const float* __restrict__ eWi0, const float* __restrict__ eWh0,
                            const float* __restrict__ eWi1, const float* __restrict__ eWh1,
                            const float* __restrict__ dWh0, const float* __restrict__ dWi1,
                            const float* __restrict__ dWh1) {
    const int tid = threadIdx.x;
    const int gid = blockIdx.x * blockDim.x + tid;
    const int stride = gridDim.x * blockDim.x;

    const __half z = __float2half(0.f);
    for (int i = gid; i < Bq * Hd; i += stride) {
        g_h0[0][i] = z; g_h0[1][i] = z;
        g_h1[0][i] = z; g_h1[1][i] = z;
    }
    if (gid == 0) g_bar = 0u;

    {
        const int total = Bq * T_ENC * FEAT;
        for (int i = gid; i < total; i += stride)
            g_X[i] = __float2half_rn(Xe[i]);
    }

    split_w(g_eWh0h, g_eWh0l, eWh0, 512, gid, stride);
    split_w(g_eWi0h, g_eWi0l, eWi0, 128, gid, stride);
    split_w(g_eWi1h, g_eWi1l, eWi1, 512, gid, stride);
    split_w(g_eWh1h, g_eWh1l, eWh1, 512, gid, stride);
    split_w(g_dWh0h, g_dWh0l, dWh0, 512, gid, stride);
    split_w(g_dWi1h, g_dWi1l, dWi1, 512, gid, stride);
    split_w(g_dWh1h, g_dWh1l, dWh1, 512, gid, stride);

    const int b = blockIdx.x;
    if (b < Bq) {
        float s = 0.0f;
        for (int i = tid; i < PRED * 8; i += blockDim.x) s += Xd[b * PRED * 8 + i];
        __shared__ float red[INTHR];
        red[tid] = s;
        __syncthreads();
        for (int off = INTHR / 2; off > 0; off >>= 1) {
            if (tid < off) red[tid] += red[tid + off];
            __syncthreads();
        }
        if (tid == 0) g_dec_in0[b] = red[0];
    }
}

// ---------------- persistent seq2seq kernel ----------------
__global__ __launch_bounds__(NTHR, 2) void seq2seq_kernel(
    const float* __restrict__ y, const int* __restrict__ tfm,
    const float* __restrict__ ebi0, const float* __restrict__ ebh0,
    const float* __restrict__ ebi1, const float* __restrict__ ebh1,
    const float* __restrict__ dWi0,
    const float* __restrict__ dbi0, const float* __restrict__ dbh0,
    const float* __restrict__ dbi1, const float* __restrict__ dbh1,
    const float* __restrict__ fcW, const float* __restrict__ fcB,
    float* __restrict__ d_out) {
    extern __shared__ __align__(128) char s_raw[];

    const int tileM = blockIdx.x >> 5;   // 0..7
    const int tileN = blockIdx.x & 31;   // 0..31
    const int bm0 = tileM * BM;
    const int hc0 = tileN * 16;
    const size_t woff512 = (size_t)tileN * 64 * 512;
    const size_t woff128 = (size_t)tileN * 64 * 128;

    float c0r[4], c1r[4];
#pragma unroll
    for (int qq = 0; qq < 4; ++qq) { c0r[qq] = 0.0f; c1r[qq] = 0.0f; }

    unsigned int phase = 0;
    int par = 0;
    float acc0[2][2][4], acc1[2][2][4];

#define ZERO_ACC(A) do { _Pragma("unroll") for (int _m = 0; _m < 2; ++_m) \
    _Pragma("unroll") for (int _j = 0; _j < 2; ++_j) \
    _Pragma("unroll") for (int _k = 0; _k < 4; ++_k) (A)[_m][_j][_k] = 0.0f; } while (0)

    // ---------------- encoder (wavefront: layer0(t=s) + layer1(t=s-1)) ----------
    for (int s = 0; s < T_ENC; ++s) {
        const __half* hr0 = g_h0[par];
        __half* hw0 = g_h0[par ^ 1];
        const __half* hr1 = g_h1[par];
        __half* hw1 = g_h1[par ^ 1];

        ZERO_ACC(acc0);
        if (s > 0) {
            ZERO_ACC(acc1);
            gemm_pipe(acc0, acc1, s_raw,
                      hr0, Hd, g_eWh0h + woff512, g_eWh0l + woff512, 8,
                      g_X + (size_t)s * FEAT, (size_t)T_ENC * FEAT,
                      g_eWi0h + woff128, g_eWi0l + woff128, 2,
                      hr0, Hd, g_eWi1h + woff512, g_eWi1l + woff512, 8,
                      hr1, Hd, g_eWh1h + woff512, g_eWh1l + woff512, 8,
                      10, bm0);
            epilogue<0>(acc0, s_raw, c0r, ebi0, ebh0, hw0, bm0, hc0, tileN,
                        (const float*)0, (const float*)0, (const int*)0, (float*)0, s,
                        (const float*)0, (const float*)0);
            epilogue<0>(acc1, s_raw, c1r, ebi1, ebh1, hw1, bm0, hc0, tileN,
                        (const float*)0, (const float*)0, (const int*)0, (float*)0, s,
                        (const float*)0, (const float*)0);
        } else {
            gemm_pipe(acc0, acc0, s_raw,
                      hr0, Hd, g_eWh0h + woff512, g_eWh0l + woff512, 8,
                      g_X + (size_t)s * FEAT, (size_t)T_ENC * FEAT,
                      g_eWi0h + woff128, g_eWi0l + woff128, 2,
                      (const __half*)0, 0, (const __half*)0, (const __half*)0, 0,
                      (const __half*)0, 0, (const __half*)0, (const __half*)0, 0,
                      10, bm0);
            epilogue<0>(acc0, s_raw, c0r, ebi0, ebh0, hw0, bm0, hc0, tileN,
                        (const float*)0, (const float*)0, (const int*)0, (float*)0, s,
                        (const float*)0, (const float*)0);
        }
        grid_bar(&phase);
        par ^= 1;
    }

    // tail stage: layer1(t=T_ENC-1) (seg2 slot, stride 512) + h0 copy
    {
        const __half* hr0 = g_h0[par];
        __half* hw0 = g_h0[par ^ 1];
        const __half* hr1 = g_h1[par];
        __half* hw1 = g_h1[par ^ 1];

        ZERO_ACC(acc0);
        gemm_pipe(acc0, acc0, s_raw,
                  hr0, Hd, g_eWi1h + woff512, g_eWi1l + woff512, 8,
                  (const __half*)0, 0, (const __half*)0, (const __half*)0, 0,
                  hr1, Hd, g_eWh1h + woff512, g_eWh1l + woff512, 8,
                  (const __half*)0, 0, (const __half*)0, (const __half*)0, 0,
                  16, bm0);
        epilogue<0>(acc0, s_raw, c1r, ebi1, ebh1, hw1, bm0, hc0, tileN,
                    (const float*)0, (const float*)0, (const int*)0, (float*)0, T_ENC,
                    (const float*)0, (const float*)0);

        for (int i = threadIdx.x; i < BM * 16; i += NTHR) {
            const int r = bm0 + (i >> 4), cc = hc0 + (i & 15);
            hw0[r * Hd + cc] = hr0[r * Hd + cc];
        }
        grid_bar(&phase);
        par ^= 1;
    }

    // ---------------- decoder ----------------
    for (int t = 0; t < PRED; ++t) {
        const __half* hr0 = g_h0[par];
        __half* hw0 = g_h0[par ^ 1];
        const __half* hr1 = g_h1[par];
        __half* hw1 = g_h1[par ^ 1];

        // stage A: gates0 = h0 @ dWh0^T  (+ din * dWi0 in epilogue)
        ZERO_ACC(acc0);
        gemm_pipe(acc0, acc0, s_raw,
                  hr0, Hd, g_dWh0h + woff512, g_dWh0l + woff512, 8,
                  (const __half*)0, 0, (const __half*)0, (const __half*)0, 0,
                  (const __half*)0, 0, (const __half*)0, (const __half*)0, 0,
                  (const __half*)0, 0, (const __half*)0, (const __half*)0, 0,
                  8, bm0);
        epilogue<1>(acc0, s_raw, c0r, dbi0, dbh0, hw0, bm0, hc0, tileN,
                    dWi0, y, tfm, d_out, t, (const float*)0, fcB);
        grid_bar(&phase);

        // stage B
        ZERO_ACC(acc0);
        gemm_pipe(acc0, acc0, s_raw,
                  hw0, Hd, g_dWi1h + woff512, g_dWi1l + woff512, 8,
                  (const __half*)0, 0, (const __half*)0, (const __half*)0, 0,
                  hr1, Hd, g_dWh1h + woff512, g_dWh1l + woff512, 8,
                  (const __half*)0, 0, (const __half*)0, (const __half*)0, 0,
                  16, bm0);
        epilogue<2>(acc0, s_raw, c1r, dbi1, dbh1, hw1, bm0, hc0, tileN,
                    (const float*)0, (const float*)0, (const int*)0, (float*)0, t,
                    fcW, (const float*)0);
        grid_bar(&phase);
        par ^= 1;
    }

    // ---------------- final output (t = PRED-1) ----------------
    if (tileN == 0 && threadIdx.x < BM) {
        const int b = bm0 + threadIdx.x;
        float out = fcB[0];
#pragma unroll
        for (int j = 0; j < 32; ++j) out += g_fc_part[j][b];
        d_out[b * PRED + (PRED - 1)] = out;
    }
}

// ---------------- harness entry ----------------
extern "C" void kernel_launch(void* const* d_in, const int* in_sizes, int n_in,
                              void* d_out, int out_size) {
    const float* Xe  = (const float*)d_in[0];
    const float* Xd  = (const float*)d_in[1];
    const float* y   = (const float*)d_in[2];
    const int*   tfm = (const int*)d_in[3];
    const float* eWi0 = (const float*)d_in[4];
    const float* eWh0 = (const float*)d_in[5];
    const float* ebi0 = (const float*)d_in[6];
    const float* ebh0 = (const float*)d_in[7];
    const float* eWi1 = (const float*)d_in[8];
    const float* eWh1 = (const float*)d_in[9];
    const float* ebi1 = (const float*)d_in[10];
    const float* ebh1 = (const float*)d_in[11];
    const float* dWi0 = (const float*)d_in[12];
    const float* dWh0 = (const float*)d_in[13];
    const float* dbi0 = (const float*)d_in[14];
    const float* dbh0 = (const float*)d_in[15];
    const float* dWi1 = (const float*)d_in[16];
    const float* dWh1 = (const float*)d_in[17];
    const float* dbi1 = (const float*)d_in[18];
    const float* dbh1 = (const float*)d_in[19];
    const float* fcW  = (const float*)d_in[20];
    const float* fcB  = (const float*)d_in[21];
    float* out = (float*)d_out;

    cudaFuncSetAttribute(seq2seq_kernel,
                         cudaFuncAttributeMaxDynamicSharedMemorySize, SMEM_BYTES);

    init_kernel<<<1024, INTHR>>>(Xd, Xe, eWi0, eWh0, eWi1, eWh1, dWh0, dWi1, dWh1);
    seq2seq_kernel<<<GRIDSZ, NTHR, SMEM_BYTES>>>(y, tfm,
                                                 ebi0, ebh0, ebi1, ebh1,
                                                 dWi0, dbi0, dbh0, dbi1, dbh1,
                                                 fcW, fcB, out);
}